// round 3
// baseline (speedup 1.0000x reference)
#include <cuda_runtime.h>

// LIF scan: mem = 0.25*mem + x[t]; spk = (mem >= 1.0); mem -= spk.
// Shape [T=100, 32, 16384] fp32. Independent across the 524288 neuron lanes;
// sequential only in T. One thread owns 4 neurons (float4), accumulator in
// registers, coalesced streaming loads/stores per timestep.

#define T_STEPS 100
#define NEURONS (32 * 16384)          // 524288
#define VEC4    (NEURONS / 4)         // 131072 float4 lanes per timestep

__global__ __launch_bounds__(256) void lif_kernel(const float4* __restrict__ x,
                                                  float4* __restrict__ out) {
    const int i = blockIdx.x * blockDim.x + threadIdx.x;  // 0..VEC4-1

    float mx = 0.f, my = 0.f, mz = 0.f, mw = 0.f;

    const float4* __restrict__ xp = x + i;
    float4* __restrict__ op = out + i;

#pragma unroll 4
    for (int t = 0; t < T_STEPS; ++t) {
        const float4 xt = xp[(long)t * VEC4];

        mx = fmaf(0.25f, mx, xt.x);
        my = fmaf(0.25f, my, xt.y);
        mz = fmaf(0.25f, mz, xt.z);
        mw = fmaf(0.25f, mw, xt.w);

        const float sx = (mx >= 1.0f) ? 1.0f : 0.0f;
        const float sy = (my >= 1.0f) ? 1.0f : 0.0f;
        const float sz = (mz >= 1.0f) ? 1.0f : 0.0f;
        const float sw = (mw >= 1.0f) ? 1.0f : 0.0f;

        mx -= sx;
        my -= sy;
        mz -= sz;
        mw -= sw;

        float4 s;
        s.x = sx; s.y = sy; s.z = sz; s.w = sw;
        op[(long)t * VEC4] = s;
    }
}

extern "C" void kernel_launch(void* const* d_in, const int* in_sizes, int n_in,
                              void* d_out, int out_size) {
    const float4* x = (const float4*)d_in[0];
    float4* out = (float4*)d_out;

    const int threads = 256;
    const int blocks = VEC4 / threads;  // 512
    lif_kernel<<<blocks, threads>>>(x, out);
}